// round 15
// baseline (speedup 1.0000x reference)
#include <cuda_runtime.h>
#include <cuda_bf16.h>
#include <cstdint>

// ===========================================================================
// PrismDecoder round 15: revert GEMM to validated round-9 config (128x64
// tile, K-chunk 64, 2-stage cp.async, 2 CTAs/SM, persistent, x4 B-frags)
// + fuse out12 into procrustes (no g_out12 roundtrip).
// ===========================================================================

#define N_VERTS 100000
#define N_FACES 200000
#define MPAD    200064            // 1563 * 128
#define MPAD1   100096            // 782  * 128
#define DIMD    512
#define GRID_P  304               // 2 x 152 SMs

// -------------------- static device scratch (zero-initialized) -------------
__device__ __nv_bfloat16 g_FH[(size_t)MPAD1 * 512];   // features hi
__device__ __nv_bfloat16 g_FL[(size_t)MPAD1 * 512];   // features lo
__device__ float         g_P [(size_t)MPAD1 * 512];   // features @ W1
__device__ __nv_bfloat16 g_A1H[(size_t)MPAD * 512];   // h1 hi
__device__ __nv_bfloat16 g_A1L[(size_t)MPAD * 512];
__device__ __nv_bfloat16 g_A2H[(size_t)MPAD * 512];   // h2 hi
__device__ __nv_bfloat16 g_A2L[(size_t)MPAD * 512];
__device__ __nv_bfloat16 g_H3H[(size_t)MPAD * 256];
__device__ __nv_bfloat16 g_H3L[(size_t)MPAD * 256];
// transposed weights [N][K] bf16 hi/lo
__device__ __nv_bfloat16 g_W1H[512 * 512];
__device__ __nv_bfloat16 g_W1L[512 * 512];
__device__ __nv_bfloat16 g_W2H[512 * 512];
__device__ __nv_bfloat16 g_W2L[512 * 512];
__device__ __nv_bfloat16 g_W3H[256 * 512];
__device__ __nv_bfloat16 g_W3L[256 * 512];
__device__ float g_summed[(size_t)N_VERTS * 3];
__device__ float g_counts[N_VERTS];

__device__ __forceinline__ __nv_bfloat16* bsel(int s) {
    switch (s) {
        case 0:  return g_FH;   case 1:  return g_FL;
        case 2:  return g_A1H;  case 3:  return g_A1L;
        case 4:  return g_A2H;  case 5:  return g_A2L;
        case 6:  return g_H3H;  case 7:  return g_H3L;
        case 8:  return g_W1H;  case 9:  return g_W1L;
        case 10: return g_W2H;  case 11: return g_W2L;
        case 12: return g_W3H;  default: return g_W3L;
    }
}

// -------------------- PTX helpers (baseline ISA) ---------------------------
__device__ __forceinline__ uint32_t smem_u32(const void* p) {
    uint32_t a;
    asm("{ .reg .u64 t; cvta.to.shared.u64 t, %1; cvt.u32.u64 %0, t; }"
        : "=r"(a) : "l"(p));
    return a;
}
__device__ __forceinline__ void cp16(uint32_t dst, const void* src) {
    asm volatile("cp.async.cg.shared.global [%0], [%1], 16;"
                 :: "r"(dst), "l"(src));
}
#define CP_COMMIT() asm volatile("cp.async.commit_group;" ::: "memory")
#define CP_WAIT(n)  asm volatile("cp.async.wait_group %0;" :: "n"(n) : "memory")

__device__ __forceinline__ void ldmx4(uint32_t r[4], uint32_t addr) {
    asm volatile("ldmatrix.sync.aligned.m8n8.x4.shared.b16 {%0,%1,%2,%3}, [%4];"
                 : "=r"(r[0]), "=r"(r[1]), "=r"(r[2]), "=r"(r[3]) : "r"(addr));
}
__device__ __forceinline__ void ldmx4p(uint32_t& r0, uint32_t& r1,
                                       uint32_t& r2, uint32_t& r3,
                                       uint32_t addr) {
    asm volatile("ldmatrix.sync.aligned.m8n8.x4.shared.b16 {%0,%1,%2,%3}, [%4];"
                 : "=r"(r0), "=r"(r1), "=r"(r2), "=r"(r3) : "r"(addr));
}
__device__ __forceinline__ void mma16816(float d[4], const uint32_t a[4],
                                         const uint32_t b[2]) {
    asm volatile(
        "mma.sync.aligned.m16n8k16.row.col.f32.bf16.bf16.f32 "
        "{%0,%1,%2,%3}, {%4,%5,%6,%7}, {%8,%9}, {%0,%1,%2,%3};"
        : "+f"(d[0]), "+f"(d[1]), "+f"(d[2]), "+f"(d[3])
        : "r"(a[0]), "r"(a[1]), "r"(a[2]), "r"(a[3]), "r"(b[0]), "r"(b[1]));
}
__device__ __forceinline__ uint32_t packbf2(__nv_bfloat16 a, __nv_bfloat16 b) {
    return (uint32_t)__bfloat16_as_ushort(a) |
           ((uint32_t)__bfloat16_as_ushort(b) << 16);
}
#define SWZC(row, c16) ((uint32_t)((row) * 128 + (((c16) * 16) ^ (((row) & 7) * 16))))

// ---------------------------------------------------------------------------
__global__ void zero_kernel() {
    int i = blockIdx.x * blockDim.x + threadIdx.x;
    if (i < N_VERTS * 3) g_summed[i] = 0.0f;
    if (i < N_VERTS)     g_counts[i] = 0.0f;
}

// weight transpose + hi/lo split:  W [K][N] fp32 -> Wt [N][K] bf16 hi/lo
__global__ void convert_w(const float* __restrict__ W, int selH, int selL, int N) {
    int idx = blockIdx.x * blockDim.x + threadIdx.x;     // n*512 + k
    if (idx >= N * 512) return;
    int n = idx >> 9, k = idx & 511;
    float v = W[(size_t)k * N + n];
    __nv_bfloat16 h = __float2bfloat16(v);
    bsel(selH)[idx] = h;
    bsel(selL)[idx] = __float2bfloat16(v - __bfloat162float(h));
}

// features fp32 -> bf16 hi/lo (elementwise, no gather)
__global__ void split_feat_kernel(const float* __restrict__ features) {
    int idx = blockIdx.x * blockDim.x + threadIdx.x;      // float4 chunks
    if (idx >= N_VERTS * 128) return;
    size_t o = (size_t)idx * 4;
    float4 p = *(const float4*)&features[o];
    __nv_bfloat16 h0 = __float2bfloat16(p.x);
    __nv_bfloat16 h1 = __float2bfloat16(p.y);
    __nv_bfloat16 h2 = __float2bfloat16(p.z);
    __nv_bfloat16 h3 = __float2bfloat16(p.w);
    __nv_bfloat16 l0 = __float2bfloat16(p.x - __bfloat162float(h0));
    __nv_bfloat16 l1 = __float2bfloat16(p.y - __bfloat162float(h1));
    __nv_bfloat16 l2 = __float2bfloat16(p.z - __bfloat162float(h2));
    __nv_bfloat16 l3 = __float2bfloat16(p.w - __bfloat162float(h3));
    *(uint2*)&g_FH[o] = make_uint2(packbf2(h0, h1), packbf2(h2, h3));
    *(uint2*)&g_FL[o] = make_uint2(packbf2(l0, l1), packbf2(l2, l3));
}

// ---------------------------------------------------------------------------
// Persistent split-bf16 HMMA GEMM (round-9 validated config):
// CTA tile 128(M)x64(N), 256 threads, 8 warps (4x2), warp tile 32x32.
// K-chunk 64 (128B rows, SW128), 2-stage cp.async (48KB/stage) -> 2 CTAs/SM.
// 3 MMA products per k-tile: Ah*Bh + Ah*Bl + Al*Bh.
// mode 0: fp32 out to g_P.  mode 1: bias+relu+split bf16.
// ---------------------------------------------------------------------------
#define GSTAGE 49152              // Ah 16K | Al 16K | Bh 8K | Bl 8K
#define GSMEM  (2 * GSTAGE)

__global__ __launch_bounds__(256, 2)
void gemm_mma_persist(int selInH, int selInL, int selWH, int selWL,
                      const float* __restrict__ bias, int mode,
                      int selOutH, int selOutL, int Ncols,
                      int nBlk, int numTiles)
{
    extern __shared__ char smem[];
    const uint32_t sb = smem_u32(smem);
    const int tid  = threadIdx.x;
    const int lane = tid & 31;
    const int warp = tid >> 5;              // 0..7
    const int warpM = (warp >> 1) * 32;     // 0,32,64,96
    const int warpN = (warp & 1) * 32;      // 0,32

    const __nv_bfloat16* __restrict__ inH = bsel(selInH);
    const __nv_bfloat16* __restrict__ inL = bsel(selInL);
    const __nv_bfloat16* __restrict__ wH  = bsel(selWH);
    const __nv_bfloat16* __restrict__ wL  = bsel(selWL);

    const int nMine = (numTiles - blockIdx.x + gridDim.x - 1) / gridDim.x;
    if (nMine <= 0) return;
    const int total = nMine * 8;            // chunk stream length

    const int aRow   = (lane & 7) + ((lane >> 3) & 1) * 8;
    const int aColSl = lane >> 4;
    const int bg     = lane >> 3;           // 0..3 (x4 group)
    const int bgRow  = lane & 7;

    float acc[2][4][4];
    #pragma unroll
    for (int i = 0; i < 2; i++)
        #pragma unroll
        for (int j = 0; j < 4; j++)
            #pragma unroll
            for (int q = 0; q < 4; q++) acc[i][j][q] = 0.0f;

    auto tile_coords = [&](int q, size_t& mB, size_t& nB) {
        int t = blockIdx.x + q * gridDim.x;
        mB = (size_t)(t / nBlk) * 128;
        nB = (size_t)(t % nBlk) * 64;
    };

    auto load_chunk = [&](int s, int stage) {
        int q = s >> 3, c = s & 7;
        size_t mBase, nBase;
        tile_coords(q, mBase, nBase);
        uint32_t base = sb + stage * GSTAGE;
        #pragma unroll
        for (int i = 0; i < 4; i++) {
            int ch = tid + i * 256;          // 0..1023
            int r = ch >> 3, c16 = ch & 7;
            uint32_t sw = SWZC(r, c16);
            size_t ga = (mBase + r) * 512 + (size_t)c * 64 + c16 * 8;
            cp16(base + sw,         inH + ga);
            cp16(base + 16384 + sw, inL + ga);
        }
        #pragma unroll
        for (int i = 0; i < 2; i++) {
            int ch = tid + i * 256;          // 0..511
            int r = ch >> 3, c16 = ch & 7;
            uint32_t sw = SWZC(r, c16);
            size_t gb = (nBase + r) * 512 + (size_t)c * 64 + c16 * 8;
            cp16(base + 32768 + sw, wH + gb);
            cp16(base + 40960 + sw, wL + gb);
        }
        CP_COMMIT();
    };

    auto epilogue = [&](int q) {
        size_t mBase, nBase;
        tile_coords(q, mBase, nBase);
        const int colq = (lane & 3) * 2;
        const int rowq = lane >> 2;
        if (mode == 0) {
            float* __restrict__ P = g_P;
            #pragma unroll
            for (int j = 0; j < 4; j++) {
                size_t col = nBase + warpN + j * 8 + colq;
                #pragma unroll
                for (int i = 0; i < 2; i++) {
                    size_t row0 = mBase + warpM + i * 16 + rowq;
                    *(float2*)&P[row0 * 512 + col] =
                        make_float2(acc[i][j][0], acc[i][j][1]);
                    *(float2*)&P[(row0 + 8) * 512 + col] =
                        make_float2(acc[i][j][2], acc[i][j][3]);
                }
            }
        } else {
            __nv_bfloat16* __restrict__ oH = bsel(selOutH);
            __nv_bfloat16* __restrict__ oL = bsel(selOutL);
            #pragma unroll
            for (int j = 0; j < 4; j++) {
                size_t col = nBase + warpN + j * 8 + colq;
                float b0 = __ldg(&bias[col]);
                float b1 = __ldg(&bias[col + 1]);
                #pragma unroll
                for (int i = 0; i < 2; i++) {
                    size_t row0 = mBase + warpM + i * 16 + rowq;
                    size_t row1 = row0 + 8;
                    float v00 = fmaxf(acc[i][j][0] + b0, 0.0f);
                    float v01 = fmaxf(acc[i][j][1] + b1, 0.0f);
                    float v10 = fmaxf(acc[i][j][2] + b0, 0.0f);
                    float v11 = fmaxf(acc[i][j][3] + b1, 0.0f);
                    __nv_bfloat16 h00 = __float2bfloat16(v00);
                    __nv_bfloat16 h01 = __float2bfloat16(v01);
                    __nv_bfloat16 h10 = __float2bfloat16(v10);
                    __nv_bfloat16 h11 = __float2bfloat16(v11);
                    __nv_bfloat16 l00 = __float2bfloat16(v00 - __bfloat162float(h00));
                    __nv_bfloat16 l01 = __float2bfloat16(v01 - __bfloat162float(h01));
                    __nv_bfloat16 l10 = __float2bfloat16(v10 - __bfloat162float(h10));
                    __nv_bfloat16 l11 = __float2bfloat16(v11 - __bfloat162float(h11));
                    *(uint32_t*)&oH[row0 * Ncols + col] = packbf2(h00, h01);
                    *(uint32_t*)&oH[row1 * Ncols + col] = packbf2(h10, h11);
                    *(uint32_t*)&oL[row0 * Ncols + col] = packbf2(l00, l01);
                    *(uint32_t*)&oL[row1 * Ncols + col] = packbf2(l10, l11);
                }
            }
        }
        #pragma unroll
        for (int i = 0; i < 2; i++)
            #pragma unroll
            for (int j = 0; j < 4; j++)
                #pragma unroll
                for (int q2 = 0; q2 < 4; q2++) acc[i][j][q2] = 0.0f;
    };

    load_chunk(0, 0);
    if (total > 1) load_chunk(1, 1);

    #pragma unroll 1
    for (int s = 0; s < total; s++) {
        if (s + 1 < total) { CP_WAIT(1); } else { CP_WAIT(0); }
        __syncthreads();

        const uint32_t aBh = sb + (s & 1) * GSTAGE;
        const uint32_t aBl = aBh + 16384;
        const uint32_t bBh = aBh + 32768;
        const uint32_t bBl = aBh + 40960;

        #pragma unroll
        for (int ks = 0; ks < 4; ks++) {
            uint32_t ah[2][4], al[2][4];
            const int cA = ks * 2 + aColSl;
            #pragma unroll
            for (int i = 0; i < 2; i++) {
                int row = warpM + i * 16 + aRow;
                uint32_t off = SWZC(row, cA);
                ldmx4(ah[i], aBh + off);
                ldmx4(al[i], aBl + off);
            }
            uint32_t bh[4][2], bl[4][2];
            #pragma unroll
            for (int jp = 0; jp < 2; jp++) {
                int row = warpN + jp * 16 + (bg >> 1) * 8 + bgRow;
                uint32_t off = SWZC(row, ks * 2 + (bg & 1));
                ldmx4p(bh[jp*2][0], bh[jp*2][1], bh[jp*2+1][0], bh[jp*2+1][1],
                       bBh + off);
                ldmx4p(bl[jp*2][0], bl[jp*2][1], bl[jp*2+1][0], bl[jp*2+1][1],
                       bBl + off);
            }
            #pragma unroll
            for (int i = 0; i < 2; i++)
                #pragma unroll
                for (int j = 0; j < 4; j++) {
                    mma16816(acc[i][j], ah[i], bh[j]);
                    mma16816(acc[i][j], ah[i], bl[j]);
                    mma16816(acc[i][j], al[i], bh[j]);
                }
        }

        __syncthreads();                     // all reads of stage (s&1) done
        if (s + 2 < total) load_chunk(s + 2, s & 1);
        if ((s & 7) == 7) epilogue(s >> 3);  // after next loads are in flight
    }
}

// ---------------------------------------------------------------------------
// h1 = relu(mean3(P[faces]) + b1) -> bf16 hi/lo.
// ---------------------------------------------------------------------------
__global__ void gather_mean_split_kernel(const int* __restrict__ faces,
                                         const float* __restrict__ b1) {
    int idx = blockIdx.x * blockDim.x + threadIdx.x;
    int f  = idx >> 7;
    int c4 = (idx & 127) << 2;
    if (f >= N_FACES) return;
    int i0 = __ldg(&faces[f * 3 + 0]);
    int i1 = __ldg(&faces[f * 3 + 1]);
    int i2 = __ldg(&faces[f * 3 + 2]);
    float4 a = *(const float4*)&g_P[(size_t)i0 * DIMD + c4];
    float4 b = *(const float4*)&g_P[(size_t)i1 * DIMD + c4];
    float4 c = *(const float4*)&g_P[(size_t)i2 * DIMD + c4];
    float4 bb = *(const float4*)&b1[c4];
    const float k = 1.0f / 3.0f;
    float v0 = fmaxf((a.x + b.x + c.x) * k + bb.x, 0.0f);
    float v1 = fmaxf((a.y + b.y + c.y) * k + bb.y, 0.0f);
    float v2 = fmaxf((a.z + b.z + c.z) * k + bb.z, 0.0f);
    float v3 = fmaxf((a.w + b.w + c.w) * k + bb.w, 0.0f);
    __nv_bfloat16 h0 = __float2bfloat16(v0);
    __nv_bfloat16 h1 = __float2bfloat16(v1);
    __nv_bfloat16 h2 = __float2bfloat16(v2);
    __nv_bfloat16 h3 = __float2bfloat16(v3);
    __nv_bfloat16 l0 = __float2bfloat16(v0 - __bfloat162float(h0));
    __nv_bfloat16 l1 = __float2bfloat16(v1 - __bfloat162float(h1));
    __nv_bfloat16 l2 = __float2bfloat16(v2 - __bfloat162float(h2));
    __nv_bfloat16 l3 = __float2bfloat16(v3 - __bfloat162float(h3));
    size_t o = (size_t)f * DIMD + c4;
    *(uint2*)&g_A1H[o] = make_uint2(packbf2(h0, h1), packbf2(h2, h3));
    *(uint2*)&g_A1L[o] = make_uint2(packbf2(l0, l1), packbf2(l2, l3));
}

// ---------------------------------------------------------------------------
// Fused: out12 = h3 @ W4 + b4, then 3x3 special procrustes + transform +
// segment atomics. One thread per face; g_out12 roundtrip eliminated.
// ---------------------------------------------------------------------------
__device__ __forceinline__ void jrot(float A[3][3], float V[3][3],
                                     int p, int q, int r) {
    float apq = A[p][q];
    if (fabsf(apq) < 1e-20f) return;
    float tau = (A[q][q] - A[p][p]) / (2.0f * apq);
    float t = copysignf(1.0f, tau) / (fabsf(tau) + sqrtf(1.0f + tau * tau));
    float c = rsqrtf(1.0f + t * t);
    float s = t * c;
    A[p][p] -= t * apq;
    A[q][q] += t * apq;
    A[p][q] = 0.0f; A[q][p] = 0.0f;
    float arp = A[r][p], arq = A[r][q];
    A[r][p] = c * arp - s * arq; A[p][r] = A[r][p];
    A[r][q] = s * arp + c * arq; A[q][r] = A[r][q];
    #pragma unroll
    for (int k = 0; k < 3; k++) {
        float vkp = V[k][p], vkq = V[k][q];
        V[k][p] = c * vkp - s * vkq;
        V[k][q] = s * vkp + c * vkq;
    }
}

__device__ __forceinline__ void cross3(const float a[3], const float b[3], float o[3]) {
    o[0] = a[1] * b[2] - a[2] * b[1];
    o[1] = a[2] * b[0] - a[0] * b[2];
    o[2] = a[0] * b[1] - a[1] * b[0];
}

__global__ __launch_bounds__(128)
void decode_kernel(const float* __restrict__ W4, const float* __restrict__ b4,
                   const float* __restrict__ verts,
                   const int*   __restrict__ faces,
                   float* __restrict__ out) {
    __shared__ float ws[256 * 12];
    for (int i = threadIdx.x; i < 256 * 12; i += blockDim.x) ws[i] = W4[i];
    __syncthreads();
    int f = blockIdx.x * blockDim.x + threadIdx.x;
    if (f >= N_FACES) return;

    // ---- out12 = h3 @ W4 + b4 ----
    const __nv_bfloat16* xh = g_H3H + (size_t)f * 256;
    const __nv_bfloat16* xl = g_H3L + (size_t)f * 256;
    float o[12];
    #pragma unroll
    for (int n = 0; n < 12; n++) o[n] = b4[n];
    for (int k = 0; k < 256; k += 8) {
        uint4 uh = *(const uint4*)&xh[k];
        uint4 ul = *(const uint4*)&xl[k];
        const uint32_t hu[4] = {uh.x, uh.y, uh.z, uh.w};
        const uint32_t lu[4] = {ul.x, ul.y, ul.z, ul.w};
        #pragma unroll
        for (int t = 0; t < 4; t++) {
            __nv_bfloat162 hb = *(const __nv_bfloat162*)&hu[t];
            __nv_bfloat162 lb = *(const __nv_bfloat162*)&lu[t];
            float v0 = __bfloat162float(hb.x) + __bfloat162float(lb.x);
            float v1 = __bfloat162float(hb.y) + __bfloat162float(lb.y);
            int kk = k + t * 2;
            #pragma unroll
            for (int n = 0; n < 12; n++) {
                o[n] = fmaf(v0, ws[kk * 12 + n], o[n]);
                o[n] = fmaf(v1, ws[(kk + 1) * 12 + n], o[n]);
            }
        }
    }

    // ---- special procrustes on o[0..8] ----
    float m[3][3];
    #pragma unroll
    for (int i = 0; i < 3; i++)
        #pragma unroll
        for (int j = 0; j < 3; j++) m[i][j] = o[3 * i + j];

    float fr = 0.0f;
    #pragma unroll
    for (int i = 0; i < 3; i++)
        #pragma unroll
        for (int j = 0; j < 3; j++) fr += m[i][j] * m[i][j];
    float inv = rsqrtf(fmaxf(fr, 1e-30f));
    #pragma unroll
    for (int i = 0; i < 3; i++)
        #pragma unroll
        for (int j = 0; j < 3; j++) m[i][j] *= inv;

    float A[3][3];
    #pragma unroll
    for (int i = 0; i < 3; i++)
        #pragma unroll
        for (int j = 0; j < 3; j++) {
            float s = 0.0f;
            #pragma unroll
            for (int k = 0; k < 3; k++) s += m[k][i] * m[k][j];
            A[i][j] = s;
        }
    float V[3][3] = {{1,0,0},{0,1,0},{0,0,1}};

    #pragma unroll
    for (int sweep = 0; sweep < 6; sweep++) {
        jrot(A, V, 0, 1, 2);
        jrot(A, V, 0, 2, 1);
        jrot(A, V, 1, 2, 0);
    }

    float w0 = A[0][0], w1 = A[1][1], w2 = A[2][2];
    int imax = (w0 >= w1) ? (w0 >= w2 ? 0 : 2) : (w1 >= w2 ? 1 : 2);
    int imin = (w0 <= w1) ? (w0 <= w2 ? 0 : 2) : (w1 <= w2 ? 1 : 2);
    if (imax == imin) imin = (imax + 1) % 3;
    int imid = 3 - imax - imin;

    float v1[3] = {V[0][imax], V[1][imax], V[2][imax]};
    float v2[3] = {V[0][imid], V[1][imid], V[2][imid]};

    float u1[3], u2[3];
    #pragma unroll
    for (int a = 0; a < 3; a++)
        u1[a] = m[a][0] * v1[0] + m[a][1] * v1[1] + m[a][2] * v1[2];
    float n1 = sqrtf(u1[0]*u1[0] + u1[1]*u1[1] + u1[2]*u1[2]);
    if (n1 > 1e-12f) {
        float in1 = 1.0f / n1;
        u1[0] *= in1; u1[1] *= in1; u1[2] *= in1;
    } else { u1[0] = 1.0f; u1[1] = 0.0f; u1[2] = 0.0f; }

    #pragma unroll
    for (int a = 0; a < 3; a++)
        u2[a] = m[a][0] * v2[0] + m[a][1] * v2[1] + m[a][2] * v2[2];
    float d = u2[0]*u1[0] + u2[1]*u1[1] + u2[2]*u1[2];
    u2[0] -= d * u1[0]; u2[1] -= d * u1[1]; u2[2] -= d * u1[2];
    float n2 = sqrtf(u2[0]*u2[0] + u2[1]*u2[1] + u2[2]*u2[2]);
    if (n2 > 1e-10f) {
        float in2 = 1.0f / n2;
        u2[0] *= in2; u2[1] *= in2; u2[2] *= in2;
    } else {
        float e[3] = {0.f, 0.f, 0.f};
        e[(fabsf(u1[0]) < 0.9f) ? 0 : 1] = 1.0f;
        cross3(u1, e, u2);
        float nn = rsqrtf(fmaxf(u2[0]*u2[0]+u2[1]*u2[1]+u2[2]*u2[2], 1e-30f));
        u2[0] *= nn; u2[1] *= nn; u2[2] *= nn;
    }

    float u3[3], v3[3];
    cross3(u1, u2, u3);
    cross3(v1, v2, v3);

    float R[3][3];
    #pragma unroll
    for (int a = 0; a < 3; a++)
        #pragma unroll
        for (int b = 0; b < 3; b++)
            R[a][b] = u1[a]*v1[b] + u2[a]*v2[b] + u3[a]*v3[b];

    float* rot_out = out + (size_t)(N_VERTS * 3) + (size_t)N_FACES * 9 + (size_t)f * 9;
    #pragma unroll
    for (int a = 0; a < 3; a++)
        #pragma unroll
        for (int b = 0; b < 3; b++)
            rot_out[a * 3 + b] = R[a][b];

    float t0 = o[9], t1 = o[10], t2 = o[11];
    float* tp_out = out + (size_t)(N_VERTS * 3) + (size_t)f * 9;
    #pragma unroll
    for (int j = 0; j < 3; j++) {
        int vi = faces[f * 3 + j];
        float p0 = verts[(size_t)vi * 3 + 0];
        float p1 = verts[(size_t)vi * 3 + 1];
        float p2 = verts[(size_t)vi * 3 + 2];
        float tpx = p0 * R[0][0] + p1 * R[1][0] + p2 * R[2][0] + t0;
        float tpy = p0 * R[0][1] + p1 * R[1][1] + p2 * R[2][1] + t1;
        float tpz = p0 * R[0][2] + p1 * R[1][2] + p2 * R[2][2] + t2;
        tp_out[j * 3 + 0] = tpx;
        tp_out[j * 3 + 1] = tpy;
        tp_out[j * 3 + 2] = tpz;
        atomicAdd(&g_summed[(size_t)vi * 3 + 0], tpx);
        atomicAdd(&g_summed[(size_t)vi * 3 + 1], tpy);
        atomicAdd(&g_summed[(size_t)vi * 3 + 2], tpz);
        atomicAdd(&g_counts[vi], 1.0f);
    }
}

__global__ void finalize_kernel(float* __restrict__ out) {
    int v = blockIdx.x * blockDim.x + threadIdx.x;
    if (v >= N_VERTS) return;
    float c = fmaxf(g_counts[v], 1.0f);
    float ic = 1.0f / c;
    out[(size_t)v * 3 + 0] = g_summed[(size_t)v * 3 + 0] * ic;
    out[(size_t)v * 3 + 1] = g_summed[(size_t)v * 3 + 1] * ic;
    out[(size_t)v * 3 + 2] = g_summed[(size_t)v * 3 + 2] * ic;
}

// ---------------------------------------------------------------------------
extern "C" void kernel_launch(void* const* d_in, const int* in_sizes, int n_in,
                              void* d_out, int out_size) {
    const float* verts    = (const float*)d_in[0];
    const float* features = (const float*)d_in[1];
    const int*   faces    = (const int*)  d_in[2];
    const float* W1 = (const float*)d_in[3];
    const float* b1 = (const float*)d_in[4];
    const float* W2 = (const float*)d_in[5];
    const float* b2 = (const float*)d_in[6];
    const float* W3 = (const float*)d_in[7];
    const float* b3 = (const float*)d_in[8];
    const float* W4 = (const float*)d_in[9];
    const float* b4 = (const float*)d_in[10];
    float* out = (float*)d_out;

    (void)in_sizes; (void)n_in; (void)out_size;

    cudaFuncSetAttribute(gemm_mma_persist,
                         cudaFuncAttributeMaxDynamicSharedMemorySize, GSMEM);

    zero_kernel<<<(N_VERTS * 3 + 255) / 256, 256>>>();

    convert_w<<<(512 * 512 + 255) / 256, 256>>>(W1, 8, 9, 512);
    convert_w<<<(512 * 512 + 255) / 256, 256>>>(W2, 10, 11, 512);
    convert_w<<<(256 * 512 + 255) / 256, 256>>>(W3, 12, 13, 256);

    split_feat_kernel<<<(N_VERTS * 128 + 255) / 256, 256>>>(features);

    // P = features @ W1t^T  (M = 100096, fp32 out, no bias)
    gemm_mma_persist<<<GRID_P, 256, GSMEM>>>(
        0, 1, 8, 9, b1, 0, 0, 0, 512, 8, (MPAD1 / 128) * 8);

    // h1 = relu(mean3(P[faces]) + b1) -> bf16 hi/lo
    gather_mean_split_kernel<<<(N_FACES * 128 + 255) / 256, 256>>>(faces, b1);

    // h2 = relu(h1 @ W2t^T + b2) -> A2
    gemm_mma_persist<<<GRID_P, 256, GSMEM>>>(
        2, 3, 10, 11, b2, 1, 4, 5, 512, 8, (MPAD / 128) * 8);

    // h3 = relu(h2 @ W3t^T + b3) -> H3
    gemm_mma_persist<<<GRID_P, 256, GSMEM>>>(
        4, 5, 12, 13, b3, 1, 6, 7, 256, 4, (MPAD / 128) * 4);

    // fused out12 + procrustes + transform + segment atomics
    decode_kernel<<<(N_FACES + 127) / 128, 128>>>(W4, b4, verts, faces, out);

    finalize_kernel<<<(N_VERTS + 255) / 256, 256>>>(out);
}

// round 16
// speedup vs baseline: 1.4678x; 1.4678x over previous
#include <cuda_runtime.h>
#include <cuda_bf16.h>
#include <cstdint>

// ===========================================================================
// PrismDecoder round 16: bank the validated round-9 optimum (1930us).
// GEMM: 128x64 tile, K-chunk 64 SW128, 2-stage cp.async, 2 CTAs/SM,
// persistent, x4 B-frags. Separate out12 + procrustes (validated).
// Only change: convert_w x3 merged into one launch; fewer launch gaps.
// ===========================================================================

#define N_VERTS 100000
#define N_FACES 200000
#define MPAD    200064            // 1563 * 128
#define MPAD1   100096            // 782  * 128
#define DIMD    512
#define GRID_P  304               // 2 x 152 SMs

// -------------------- static device scratch (zero-initialized) -------------
__device__ __nv_bfloat16 g_FH[(size_t)MPAD1 * 512];   // features hi
__device__ __nv_bfloat16 g_FL[(size_t)MPAD1 * 512];   // features lo
__device__ float         g_P [(size_t)MPAD1 * 512];   // features @ W1
__device__ __nv_bfloat16 g_A1H[(size_t)MPAD * 512];   // h1 hi
__device__ __nv_bfloat16 g_A1L[(size_t)MPAD * 512];
__device__ __nv_bfloat16 g_A2H[(size_t)MPAD * 512];   // h2 hi
__device__ __nv_bfloat16 g_A2L[(size_t)MPAD * 512];
__device__ __nv_bfloat16 g_H3H[(size_t)MPAD * 256];
__device__ __nv_bfloat16 g_H3L[(size_t)MPAD * 256];
// transposed weights [N][K] bf16 hi/lo
__device__ __nv_bfloat16 g_W1H[512 * 512];
__device__ __nv_bfloat16 g_W1L[512 * 512];
__device__ __nv_bfloat16 g_W2H[512 * 512];
__device__ __nv_bfloat16 g_W2L[512 * 512];
__device__ __nv_bfloat16 g_W3H[256 * 512];
__device__ __nv_bfloat16 g_W3L[256 * 512];
__device__ float g_out12[(size_t)N_FACES * 12];
__device__ float g_summed[(size_t)N_VERTS * 3];
__device__ float g_counts[N_VERTS];

__device__ __forceinline__ __nv_bfloat16* bsel(int s) {
    switch (s) {
        case 0:  return g_FH;   case 1:  return g_FL;
        case 2:  return g_A1H;  case 3:  return g_A1L;
        case 4:  return g_A2H;  case 5:  return g_A2L;
        case 6:  return g_H3H;  case 7:  return g_H3L;
        case 8:  return g_W1H;  case 9:  return g_W1L;
        case 10: return g_W2H;  case 11: return g_W2L;
        case 12: return g_W3H;  default: return g_W3L;
    }
}

// -------------------- PTX helpers (baseline ISA) ---------------------------
__device__ __forceinline__ uint32_t smem_u32(const void* p) {
    uint32_t a;
    asm("{ .reg .u64 t; cvta.to.shared.u64 t, %1; cvt.u32.u64 %0, t; }"
        : "=r"(a) : "l"(p));
    return a;
}
__device__ __forceinline__ void cp16(uint32_t dst, const void* src) {
    asm volatile("cp.async.cg.shared.global [%0], [%1], 16;"
                 :: "r"(dst), "l"(src));
}
#define CP_COMMIT() asm volatile("cp.async.commit_group;" ::: "memory")
#define CP_WAIT(n)  asm volatile("cp.async.wait_group %0;" :: "n"(n) : "memory")

__device__ __forceinline__ void ldmx4(uint32_t r[4], uint32_t addr) {
    asm volatile("ldmatrix.sync.aligned.m8n8.x4.shared.b16 {%0,%1,%2,%3}, [%4];"
                 : "=r"(r[0]), "=r"(r[1]), "=r"(r[2]), "=r"(r[3]) : "r"(addr));
}
__device__ __forceinline__ void ldmx4p(uint32_t& r0, uint32_t& r1,
                                       uint32_t& r2, uint32_t& r3,
                                       uint32_t addr) {
    asm volatile("ldmatrix.sync.aligned.m8n8.x4.shared.b16 {%0,%1,%2,%3}, [%4];"
                 : "=r"(r0), "=r"(r1), "=r"(r2), "=r"(r3) : "r"(addr));
}
__device__ __forceinline__ void mma16816(float d[4], const uint32_t a[4],
                                         const uint32_t b[2]) {
    asm volatile(
        "mma.sync.aligned.m16n8k16.row.col.f32.bf16.bf16.f32 "
        "{%0,%1,%2,%3}, {%4,%5,%6,%7}, {%8,%9}, {%0,%1,%2,%3};"
        : "+f"(d[0]), "+f"(d[1]), "+f"(d[2]), "+f"(d[3])
        : "r"(a[0]), "r"(a[1]), "r"(a[2]), "r"(a[3]), "r"(b[0]), "r"(b[1]));
}
__device__ __forceinline__ uint32_t packbf2(__nv_bfloat16 a, __nv_bfloat16 b) {
    return (uint32_t)__bfloat16_as_ushort(a) |
           ((uint32_t)__bfloat16_as_ushort(b) << 16);
}
#define SWZC(row, c16) ((uint32_t)((row) * 128 + (((c16) * 16) ^ (((row) & 7) * 16))))

// ---------------------------------------------------------------------------
__global__ void zero_kernel() {
    int i = blockIdx.x * blockDim.x + threadIdx.x;
    if (i < N_VERTS * 3) g_summed[i] = 0.0f;
    if (i < N_VERTS)     g_counts[i] = 0.0f;
}

// all three weight transposes + hi/lo splits in one launch.
// idx space: [0, 512*512) -> W1, [512*512, 2*512*512) -> W2,
//            [2*512*512, 2*512*512 + 256*512) -> W3
__global__ void convert_w_all(const float* __restrict__ W1,
                              const float* __restrict__ W2,
                              const float* __restrict__ W3) {
    int idx = blockIdx.x * blockDim.x + threadIdx.x;
    const int S = 512 * 512;
    const float* W;
    __nv_bfloat16 *dH, *dL;
    int N, local;
    if (idx < S)            { W = W1; dH = g_W1H; dL = g_W1L; N = 512; local = idx; }
    else if (idx < 2 * S)   { W = W2; dH = g_W2H; dL = g_W2L; N = 512; local = idx - S; }
    else if (idx < 2 * S + 256 * 512) {
        W = W3; dH = g_W3H; dL = g_W3L; N = 256; local = idx - 2 * S;
    } else return;
    int n = local >> 9, k = local & 511;
    float v = W[(size_t)k * N + n];
    __nv_bfloat16 h = __float2bfloat16(v);
    dH[local] = h;
    dL[local] = __float2bfloat16(v - __bfloat162float(h));
}

// features fp32 -> bf16 hi/lo (elementwise, no gather)
__global__ void split_feat_kernel(const float* __restrict__ features) {
    int idx = blockIdx.x * blockDim.x + threadIdx.x;      // float4 chunks
    if (idx >= N_VERTS * 128) return;
    size_t o = (size_t)idx * 4;
    float4 p = *(const float4*)&features[o];
    __nv_bfloat16 h0 = __float2bfloat16(p.x);
    __nv_bfloat16 h1 = __float2bfloat16(p.y);
    __nv_bfloat16 h2 = __float2bfloat16(p.z);
    __nv_bfloat16 h3 = __float2bfloat16(p.w);
    __nv_bfloat16 l0 = __float2bfloat16(p.x - __bfloat162float(h0));
    __nv_bfloat16 l1 = __float2bfloat16(p.y - __bfloat162float(h1));
    __nv_bfloat16 l2 = __float2bfloat16(p.z - __bfloat162float(h2));
    __nv_bfloat16 l3 = __float2bfloat16(p.w - __bfloat162float(h3));
    *(uint2*)&g_FH[o] = make_uint2(packbf2(h0, h1), packbf2(h2, h3));
    *(uint2*)&g_FL[o] = make_uint2(packbf2(l0, l1), packbf2(l2, l3));
}

// ---------------------------------------------------------------------------
// Persistent split-bf16 HMMA GEMM (round-9 validated config):
// CTA tile 128(M)x64(N), 256 threads, 8 warps (4x2), warp tile 32x32.
// K-chunk 64 (128B rows, SW128), 2-stage cp.async (48KB/stage) -> 2 CTAs/SM.
// 3 MMA products per k-tile: Ah*Bh + Ah*Bl + Al*Bh.
// mode 0: fp32 out to g_P.  mode 1: bias+relu+split bf16.
// ---------------------------------------------------------------------------
#define GSTAGE 49152              // Ah 16K | Al 16K | Bh 8K | Bl 8K
#define GSMEM  (2 * GSTAGE)

__global__ __launch_bounds__(256, 2)
void gemm_mma_persist(int selInH, int selInL, int selWH, int selWL,
                      const float* __restrict__ bias, int mode,
                      int selOutH, int selOutL, int Ncols,
                      int nBlk, int numTiles)
{
    extern __shared__ char smem[];
    const uint32_t sb = smem_u32(smem);
    const int tid  = threadIdx.x;
    const int lane = tid & 31;
    const int warp = tid >> 5;              // 0..7
    const int warpM = (warp >> 1) * 32;     // 0,32,64,96
    const int warpN = (warp & 1) * 32;      // 0,32

    const __nv_bfloat16* __restrict__ inH = bsel(selInH);
    const __nv_bfloat16* __restrict__ inL = bsel(selInL);
    const __nv_bfloat16* __restrict__ wH  = bsel(selWH);
    const __nv_bfloat16* __restrict__ wL  = bsel(selWL);

    const int nMine = (numTiles - blockIdx.x + gridDim.x - 1) / gridDim.x;
    if (nMine <= 0) return;
    const int total = nMine * 8;            // chunk stream length

    const int aRow   = (lane & 7) + ((lane >> 3) & 1) * 8;
    const int aColSl = lane >> 4;
    const int bg     = lane >> 3;           // 0..3 (x4 group)
    const int bgRow  = lane & 7;

    float acc[2][4][4];
    #pragma unroll
    for (int i = 0; i < 2; i++)
        #pragma unroll
        for (int j = 0; j < 4; j++)
            #pragma unroll
            for (int q = 0; q < 4; q++) acc[i][j][q] = 0.0f;

    auto tile_coords = [&](int q, size_t& mB, size_t& nB) {
        int t = blockIdx.x + q * gridDim.x;
        mB = (size_t)(t / nBlk) * 128;
        nB = (size_t)(t % nBlk) * 64;
    };

    auto load_chunk = [&](int s, int stage) {
        int q = s >> 3, c = s & 7;
        size_t mBase, nBase;
        tile_coords(q, mBase, nBase);
        uint32_t base = sb + stage * GSTAGE;
        #pragma unroll
        for (int i = 0; i < 4; i++) {
            int ch = tid + i * 256;          // 0..1023
            int r = ch >> 3, c16 = ch & 7;
            uint32_t sw = SWZC(r, c16);
            size_t ga = (mBase + r) * 512 + (size_t)c * 64 + c16 * 8;
            cp16(base + sw,         inH + ga);
            cp16(base + 16384 + sw, inL + ga);
        }
        #pragma unroll
        for (int i = 0; i < 2; i++) {
            int ch = tid + i * 256;          // 0..511
            int r = ch >> 3, c16 = ch & 7;
            uint32_t sw = SWZC(r, c16);
            size_t gb = (nBase + r) * 512 + (size_t)c * 64 + c16 * 8;
            cp16(base + 32768 + sw, wH + gb);
            cp16(base + 40960 + sw, wL + gb);
        }
        CP_COMMIT();
    };

    auto epilogue = [&](int q) {
        size_t mBase, nBase;
        tile_coords(q, mBase, nBase);
        const int colq = (lane & 3) * 2;
        const int rowq = lane >> 2;
        if (mode == 0) {
            float* __restrict__ P = g_P;
            #pragma unroll
            for (int j = 0; j < 4; j++) {
                size_t col = nBase + warpN + j * 8 + colq;
                #pragma unroll
                for (int i = 0; i < 2; i++) {
                    size_t row0 = mBase + warpM + i * 16 + rowq;
                    *(float2*)&P[row0 * 512 + col] =
                        make_float2(acc[i][j][0], acc[i][j][1]);
                    *(float2*)&P[(row0 + 8) * 512 + col] =
                        make_float2(acc[i][j][2], acc[i][j][3]);
                }
            }
        } else {
            __nv_bfloat16* __restrict__ oH = bsel(selOutH);
            __nv_bfloat16* __restrict__ oL = bsel(selOutL);
            #pragma unroll
            for (int j = 0; j < 4; j++) {
                size_t col = nBase + warpN + j * 8 + colq;
                float b0 = __ldg(&bias[col]);
                float b1 = __ldg(&bias[col + 1]);
                #pragma unroll
                for (int i = 0; i < 2; i++) {
                    size_t row0 = mBase + warpM + i * 16 + rowq;
                    size_t row1 = row0 + 8;
                    float v00 = fmaxf(acc[i][j][0] + b0, 0.0f);
                    float v01 = fmaxf(acc[i][j][1] + b1, 0.0f);
                    float v10 = fmaxf(acc[i][j][2] + b0, 0.0f);
                    float v11 = fmaxf(acc[i][j][3] + b1, 0.0f);
                    __nv_bfloat16 h00 = __float2bfloat16(v00);
                    __nv_bfloat16 h01 = __float2bfloat16(v01);
                    __nv_bfloat16 h10 = __float2bfloat16(v10);
                    __nv_bfloat16 h11 = __float2bfloat16(v11);
                    __nv_bfloat16 l00 = __float2bfloat16(v00 - __bfloat162float(h00));
                    __nv_bfloat16 l01 = __float2bfloat16(v01 - __bfloat162float(h01));
                    __nv_bfloat16 l10 = __float2bfloat16(v10 - __bfloat162float(h10));
                    __nv_bfloat16 l11 = __float2bfloat16(v11 - __bfloat162float(h11));
                    *(uint32_t*)&oH[row0 * Ncols + col] = packbf2(h00, h01);
                    *(uint32_t*)&oH[row1 * Ncols + col] = packbf2(h10, h11);
                    *(uint32_t*)&oL[row0 * Ncols + col] = packbf2(l00, l01);
                    *(uint32_t*)&oL[row1 * Ncols + col] = packbf2(l10, l11);
                }
            }
        }
        #pragma unroll
        for (int i = 0; i < 2; i++)
            #pragma unroll
            for (int j = 0; j < 4; j++)
                #pragma unroll
                for (int q2 = 0; q2 < 4; q2++) acc[i][j][q2] = 0.0f;
    };

    load_chunk(0, 0);
    if (total > 1) load_chunk(1, 1);

    #pragma unroll 1
    for (int s = 0; s < total; s++) {
        if (s + 1 < total) { CP_WAIT(1); } else { CP_WAIT(0); }
        __syncthreads();

        const uint32_t aBh = sb + (s & 1) * GSTAGE;
        const uint32_t aBl = aBh + 16384;
        const uint32_t bBh = aBh + 32768;
        const uint32_t bBl = aBh + 40960;

        #pragma unroll
        for (int ks = 0; ks < 4; ks++) {
            uint32_t ah[2][4], al[2][4];
            const int cA = ks * 2 + aColSl;
            #pragma unroll
            for (int i = 0; i < 2; i++) {
                int row = warpM + i * 16 + aRow;
                uint32_t off = SWZC(row, cA);
                ldmx4(ah[i], aBh + off);
                ldmx4(al[i], aBl + off);
            }
            uint32_t bh[4][2], bl[4][2];
            #pragma unroll
            for (int jp = 0; jp < 2; jp++) {
                int row = warpN + jp * 16 + (bg >> 1) * 8 + bgRow;
                uint32_t off = SWZC(row, ks * 2 + (bg & 1));
                ldmx4p(bh[jp*2][0], bh[jp*2][1], bh[jp*2+1][0], bh[jp*2+1][1],
                       bBh + off);
                ldmx4p(bl[jp*2][0], bl[jp*2][1], bl[jp*2+1][0], bl[jp*2+1][1],
                       bBl + off);
            }
            #pragma unroll
            for (int i = 0; i < 2; i++)
                #pragma unroll
                for (int j = 0; j < 4; j++) {
                    mma16816(acc[i][j], ah[i], bh[j]);
                    mma16816(acc[i][j], ah[i], bl[j]);
                    mma16816(acc[i][j], al[i], bh[j]);
                }
        }

        __syncthreads();                     // all reads of stage (s&1) done
        if (s + 2 < total) load_chunk(s + 2, s & 1);
        if ((s & 7) == 7) epilogue(s >> 3);  // after next loads are in flight
    }
}

// ---------------------------------------------------------------------------
// h1 = relu(mean3(P[faces]) + b1) -> bf16 hi/lo.
// ---------------------------------------------------------------------------
__global__ void gather_mean_split_kernel(const int* __restrict__ faces,
                                         const float* __restrict__ b1) {
    int idx = blockIdx.x * blockDim.x + threadIdx.x;
    int f  = idx >> 7;
    int c4 = (idx & 127) << 2;
    if (f >= N_FACES) return;
    int i0 = __ldg(&faces[f * 3 + 0]);
    int i1 = __ldg(&faces[f * 3 + 1]);
    int i2 = __ldg(&faces[f * 3 + 2]);
    float4 a = *(const float4*)&g_P[(size_t)i0 * DIMD + c4];
    float4 b = *(const float4*)&g_P[(size_t)i1 * DIMD + c4];
    float4 c = *(const float4*)&g_P[(size_t)i2 * DIMD + c4];
    float4 bb = *(const float4*)&b1[c4];
    const float k = 1.0f / 3.0f;
    float v0 = fmaxf((a.x + b.x + c.x) * k + bb.x, 0.0f);
    float v1 = fmaxf((a.y + b.y + c.y) * k + bb.y, 0.0f);
    float v2 = fmaxf((a.z + b.z + c.z) * k + bb.z, 0.0f);
    float v3 = fmaxf((a.w + b.w + c.w) * k + bb.w, 0.0f);
    __nv_bfloat16 h0 = __float2bfloat16(v0);
    __nv_bfloat16 h1 = __float2bfloat16(v1);
    __nv_bfloat16 h2 = __float2bfloat16(v2);
    __nv_bfloat16 h3 = __float2bfloat16(v3);
    __nv_bfloat16 l0 = __float2bfloat16(v0 - __bfloat162float(h0));
    __nv_bfloat16 l1 = __float2bfloat16(v1 - __bfloat162float(h1));
    __nv_bfloat16 l2 = __float2bfloat16(v2 - __bfloat162float(h2));
    __nv_bfloat16 l3 = __float2bfloat16(v3 - __bfloat162float(h3));
    size_t o = (size_t)f * DIMD + c4;
    *(uint2*)&g_A1H[o] = make_uint2(packbf2(h0, h1), packbf2(h2, h3));
    *(uint2*)&g_A1L[o] = make_uint2(packbf2(l0, l1), packbf2(l2, l3));
}

// ---------------------------------------------------------------------------
// out12 = (h3_hi + h3_lo) @ W4 + b4
// ---------------------------------------------------------------------------
__global__ __launch_bounds__(128)
void out12_kernel(const float* __restrict__ W4, const float* __restrict__ b4) {
    __shared__ float ws[256 * 12];
    for (int i = threadIdx.x; i < 256 * 12; i += blockDim.x) ws[i] = W4[i];
    __syncthreads();
    int r = blockIdx.x * blockDim.x + threadIdx.x;
    if (r >= N_FACES) return;
    const __nv_bfloat16* xh = g_H3H + (size_t)r * 256;
    const __nv_bfloat16* xl = g_H3L + (size_t)r * 256;
    float acc[12];
    #pragma unroll
    for (int n = 0; n < 12; n++) acc[n] = b4[n];
    for (int k = 0; k < 256; k += 8) {
        uint4 uh = *(const uint4*)&xh[k];
        uint4 ul = *(const uint4*)&xl[k];
        const uint32_t hu[4] = {uh.x, uh.y, uh.z, uh.w};
        const uint32_t lu[4] = {ul.x, ul.y, ul.z, ul.w};
        #pragma unroll
        for (int t = 0; t < 4; t++) {
            __nv_bfloat162 hb = *(const __nv_bfloat162*)&hu[t];
            __nv_bfloat162 lb = *(const __nv_bfloat162*)&lu[t];
            float v0 = __bfloat162float(hb.x) + __bfloat162float(lb.x);
            float v1 = __bfloat162float(hb.y) + __bfloat162float(lb.y);
            int kk = k + t * 2;
            #pragma unroll
            for (int n = 0; n < 12; n++) {
                acc[n] = fmaf(v0, ws[kk * 12 + n], acc[n]);
                acc[n] = fmaf(v1, ws[(kk + 1) * 12 + n], acc[n]);
            }
        }
    }
    #pragma unroll
    for (int n = 0; n < 12; n++) g_out12[(size_t)r * 12 + n] = acc[n];
}

// ---------------------------------------------------------------------------
// 3x3 Jacobi + special procrustes + transform + segment atomics
// ---------------------------------------------------------------------------
__device__ __forceinline__ void jrot(float A[3][3], float V[3][3],
                                     int p, int q, int r) {
    float apq = A[p][q];
    if (fabsf(apq) < 1e-20f) return;
    float tau = (A[q][q] - A[p][p]) / (2.0f * apq);
    float t = copysignf(1.0f, tau) / (fabsf(tau) + sqrtf(1.0f + tau * tau));
    float c = rsqrtf(1.0f + t * t);
    float s = t * c;
    A[p][p] -= t * apq;
    A[q][q] += t * apq;
    A[p][q] = 0.0f; A[q][p] = 0.0f;
    float arp = A[r][p], arq = A[r][q];
    A[r][p] = c * arp - s * arq; A[p][r] = A[r][p];
    A[r][q] = s * arp + c * arq; A[q][r] = A[r][q];
    #pragma unroll
    for (int k = 0; k < 3; k++) {
        float vkp = V[k][p], vkq = V[k][q];
        V[k][p] = c * vkp - s * vkq;
        V[k][q] = s * vkp + c * vkq;
    }
}

__device__ __forceinline__ void cross3(const float a[3], const float b[3], float o[3]) {
    o[0] = a[1] * b[2] - a[2] * b[1];
    o[1] = a[2] * b[0] - a[0] * b[2];
    o[2] = a[0] * b[1] - a[1] * b[0];
}

__global__ __launch_bounds__(256)
void procrustes_kernel(const float* __restrict__ verts,
                       const int*   __restrict__ faces,
                       float* __restrict__ out) {
    int f = blockIdx.x * blockDim.x + threadIdx.x;
    if (f >= N_FACES) return;

    float o[12];
    #pragma unroll
    for (int i = 0; i < 12; i++) o[i] = g_out12[(size_t)f * 12 + i];

    float m[3][3];
    #pragma unroll
    for (int i = 0; i < 3; i++)
        #pragma unroll
        for (int j = 0; j < 3; j++) m[i][j] = o[3 * i + j];

    float fr = 0.0f;
    #pragma unroll
    for (int i = 0; i < 3; i++)
        #pragma unroll
        for (int j = 0; j < 3; j++) fr += m[i][j] * m[i][j];
    float inv = rsqrtf(fmaxf(fr, 1e-30f));
    #pragma unroll
    for (int i = 0; i < 3; i++)
        #pragma unroll
        for (int j = 0; j < 3; j++) m[i][j] *= inv;

    float A[3][3];
    #pragma unroll
    for (int i = 0; i < 3; i++)
        #pragma unroll
        for (int j = 0; j < 3; j++) {
            float s = 0.0f;
            #pragma unroll
            for (int k = 0; k < 3; k++) s += m[k][i] * m[k][j];
            A[i][j] = s;
        }
    float V[3][3] = {{1,0,0},{0,1,0},{0,0,1}};

    #pragma unroll
    for (int sweep = 0; sweep < 6; sweep++) {
        jrot(A, V, 0, 1, 2);
        jrot(A, V, 0, 2, 1);
        jrot(A, V, 1, 2, 0);
    }

    float w0 = A[0][0], w1 = A[1][1], w2 = A[2][2];
    int imax = (w0 >= w1) ? (w0 >= w2 ? 0 : 2) : (w1 >= w2 ? 1 : 2);
    int imin = (w0 <= w1) ? (w0 <= w2 ? 0 : 2) : (w1 <= w2 ? 1 : 2);
    if (imax == imin) imin = (imax + 1) % 3;
    int imid = 3 - imax - imin;

    float v1[3] = {V[0][imax], V[1][imax], V[2][imax]};
    float v2[3] = {V[0][imid], V[1][imid], V[2][imid]};

    float u1[3], u2[3];
    #pragma unroll
    for (int a = 0; a < 3; a++)
        u1[a] = m[a][0] * v1[0] + m[a][1] * v1[1] + m[a][2] * v1[2];
    float n1 = sqrtf(u1[0]*u1[0] + u1[1]*u1[1] + u1[2]*u1[2]);
    if (n1 > 1e-12f) {
        float in1 = 1.0f / n1;
        u1[0] *= in1; u1[1] *= in1; u1[2] *= in1;
    } else { u1[0] = 1.0f; u1[1] = 0.0f; u1[2] = 0.0f; }

    #pragma unroll
    for (int a = 0; a < 3; a++)
        u2[a] = m[a][0] * v2[0] + m[a][1] * v2[1] + m[a][2] * v2[2];
    float d = u2[0]*u1[0] + u2[1]*u1[1] + u2[2]*u1[2];
    u2[0] -= d * u1[0]; u2[1] -= d * u1[1]; u2[2] -= d * u1[2];
    float n2 = sqrtf(u2[0]*u2[0] + u2[1]*u2[1] + u2[2]*u2[2]);
    if (n2 > 1e-10f) {
        float in2 = 1.0f / n2;
        u2[0] *= in2; u2[1] *= in2; u2[2] *= in2;
    } else {
        float e[3] = {0.f, 0.f, 0.f};
        e[(fabsf(u1[0]) < 0.9f) ? 0 : 1] = 1.0f;
        cross3(u1, e, u2);
        float nn = rsqrtf(fmaxf(u2[0]*u2[0]+u2[1]*u2[1]+u2[2]*u2[2], 1e-30f));
        u2[0] *= nn; u2[1] *= nn; u2[2] *= nn;
    }

    float u3[3], v3[3];
    cross3(u1, u2, u3);
    cross3(v1, v2, v3);

    float R[3][3];
    #pragma unroll
    for (int a = 0; a < 3; a++)
        #pragma unroll
        for (int b = 0; b < 3; b++)
            R[a][b] = u1[a]*v1[b] + u2[a]*v2[b] + u3[a]*v3[b];

    float* rot_out = out + (size_t)(N_VERTS * 3) + (size_t)N_FACES * 9 + (size_t)f * 9;
    #pragma unroll
    for (int a = 0; a < 3; a++)
        #pragma unroll
        for (int b = 0; b < 3; b++)
            rot_out[a * 3 + b] = R[a][b];

    float t0 = o[9], t1 = o[10], t2 = o[11];
    float* tp_out = out + (size_t)(N_VERTS * 3) + (size_t)f * 9;
    #pragma unroll
    for (int j = 0; j < 3; j++) {
        int vi = faces[f * 3 + j];
        float p0 = verts[(size_t)vi * 3 + 0];
        float p1 = verts[(size_t)vi * 3 + 1];
        float p2 = verts[(size_t)vi * 3 + 2];
        float tpx = p0 * R[0][0] + p1 * R[1][0] + p2 * R[2][0] + t0;
        float tpy = p0 * R[0][1] + p1 * R[1][1] + p2 * R[2][1] + t1;
        float tpz = p0 * R[0][2] + p1 * R[1][2] + p2 * R[2][2] + t2;
        tp_out[j * 3 + 0] = tpx;
        tp_out[j * 3 + 1] = tpy;
        tp_out[j * 3 + 2] = tpz;
        atomicAdd(&g_summed[(size_t)vi * 3 + 0], tpx);
        atomicAdd(&g_summed[(size_t)vi * 3 + 1], tpy);
        atomicAdd(&g_summed[(size_t)vi * 3 + 2], tpz);
        atomicAdd(&g_counts[vi], 1.0f);
    }
}

__global__ void finalize_kernel(float* __restrict__ out) {
    int v = blockIdx.x * blockDim.x + threadIdx.x;
    if (v >= N_VERTS) return;
    float c = fmaxf(g_counts[v], 1.0f);
    float ic = 1.0f / c;
    out[(size_t)v * 3 + 0] = g_summed[(size_t)v * 3 + 0] * ic;
    out[(size_t)v * 3 + 1] = g_summed[(size_t)v * 3 + 1] * ic;
    out[(size_t)v * 3 + 2] = g_summed[(size_t)v * 3 + 2] * ic;
}

// ---------------------------------------------------------------------------
extern "C" void kernel_launch(void* const* d_in, const int* in_sizes, int n_in,
                              void* d_out, int out_size) {
    const float* verts    = (const float*)d_in[0];
    const float* features = (const float*)d_in[1];
    const int*   faces    = (const int*)  d_in[2];
    const float* W1 = (const float*)d_in[3];
    const float* b1 = (const float*)d_in[4];
    const float* W2 = (const float*)d_in[5];
    const float* b2 = (const float*)d_in[6];
    const float* W3 = (const float*)d_in[7];
    const float* b3 = (const float*)d_in[8];
    const float* W4 = (const float*)d_in[9];
    const float* b4 = (const float*)d_in[10];
    float* out = (float*)d_out;

    (void)in_sizes; (void)n_in; (void)out_size;

    cudaFuncSetAttribute(gemm_mma_persist,
                         cudaFuncAttributeMaxDynamicSharedMemorySize, GSMEM);

    zero_kernel<<<(N_VERTS * 3 + 255) / 256, 256>>>();

    // all weight conversions in one launch
    {
        int total = 2 * 512 * 512 + 256 * 512;
        convert_w_all<<<(total + 255) / 256, 256>>>(W1, W2, W3);
    }

    split_feat_kernel<<<(N_VERTS * 128 + 255) / 256, 256>>>(features);

    // P = features @ W1t^T  (M = 100096, fp32 out, no bias)
    gemm_mma_persist<<<GRID_P, 256, GSMEM>>>(
        0, 1, 8, 9, b1, 0, 0, 0, 512, 8, (MPAD1 / 128) * 8);

    // h1 = relu(mean3(P[faces]) + b1) -> bf16 hi/lo
    gather_mean_split_kernel<<<(N_FACES * 128 + 255) / 256, 256>>>(faces, b1);

    // h2 = relu(h1 @ W2t^T + b2) -> A2
    gemm_mma_persist<<<GRID_P, 256, GSMEM>>>(
        2, 3, 10, 11, b2, 1, 4, 5, 512, 8, (MPAD / 128) * 8);

    // h3 = relu(h2 @ W3t^T + b3) -> H3
    gemm_mma_persist<<<GRID_P, 256, GSMEM>>>(
        4, 5, 12, 13, b3, 1, 6, 7, 256, 4, (MPAD / 128) * 4);

    out12_kernel<<<(N_FACES + 127) / 128, 128>>>(W4, b4);

    procrustes_kernel<<<(N_FACES + 255) / 256, 256>>>(verts, faces, out);

    finalize_kernel<<<(N_VERTS + 255) / 256, 256>>>(out);
}